// round 9
// baseline (speedup 1.0000x reference)
#include <cuda_runtime.h>
#include <cstdint>

#define DIM 85
#define B_ROWS 262144
#define TROWS 64
#define THREADS 256
#define NT (B_ROWS / TROWS)        // 4096 tiles
#define GRID 296                   // 2 persistent CTAs per SM
#define TILE_F (TROWS * DIM)       // 5440 floats per array per tile
#define TILE_B (TILE_F * 4)        // 21760 bytes
#define STAGE_B (2 * TILE_B)       // 43520 bytes (in + tg)

#define OFF_MBAR 0                 // 2 mbarriers, 8 B each
#define OFF_SP   16
#define OFF_ST   (OFF_SP + THREADS * 4)
#define OFF_SU   (OFF_ST + THREADS * 4)
#define OFF_DATA (OFF_SU + THREADS * 4)          // 3088 -> pad to 16
#define SMEM_TOTAL (OFF_DATA + 2 * STAGE_B)      // ~90128 B -> 2 CTAs/SM

__device__ float g_partials[GRID];
__device__ int   g_count = 0;

__device__ __forceinline__ void mbar_init(uint32_t mbar, uint32_t cnt) {
    asm volatile("mbarrier.init.shared.b64 [%0], %1;" :: "r"(mbar), "r"(cnt) : "memory");
}
__device__ __forceinline__ void mbar_expect_tx(uint32_t mbar, uint32_t bytes) {
    asm volatile("mbarrier.arrive.expect_tx.shared.b64 _, [%0], %1;"
                 :: "r"(mbar), "r"(bytes) : "memory");
}
__device__ __forceinline__ void mbar_wait(uint32_t mbar, uint32_t parity) {
    asm volatile(
        "{\n\t"
        ".reg .pred P;\n\t"
        "W_%=:\n\t"
        "mbarrier.try_wait.parity.acquire.cta.shared::cta.b64 P, [%0], %1, 0x989680;\n\t"
        "@P bra D_%=;\n\t"
        "bra W_%=;\n\t"
        "D_%=:\n\t"
        "}" :: "r"(mbar), "r"(parity) : "memory");
}
__device__ __forceinline__ void bulk_g2s(uint32_t dst, const void* src,
                                         uint32_t bytes, uint32_t mbar) {
    asm volatile(
        "cp.async.bulk.shared::cta.global.mbarrier::complete_tx::bytes [%0], [%1], %2, [%3];"
        :: "r"(dst), "l"(src), "r"(bytes), "r"(mbar) : "memory");
}

__global__ __launch_bounds__(THREADS)
void qfd_tma2(const float* __restrict__ in, const float* __restrict__ tg,
              float* __restrict__ out)
{
    extern __shared__ __align__(16) unsigned char smraw[];
    float* sP = (float*)(smraw + OFF_SP);
    float* sT = (float*)(smraw + OFF_ST);
    float* sU = (float*)(smraw + OFF_SU);
    __shared__ float warp_part[THREADS / 32];
    __shared__ bool  s_is_last;

    const int tid = threadIdx.x;
    const int row = tid & (TROWS - 1);                     // 0..63
    const int seg = tid >> 6;                              // 0..3
    const int kbeg = (seg == 0) ? 0 : (1 + 21 * seg);      // 0,22,43,64
    const int kcnt = (seg == 0) ? 22 : 21;
    const float fkbeg = (float)kbeg;

    const uint32_t mb0 = (uint32_t)__cvta_generic_to_shared(smraw + OFF_MBAR);
    const uint32_t data_s = (uint32_t)__cvta_generic_to_shared(smraw + OFF_DATA);

    if (tid == 0) {
        mbar_init(mb0, 1);
        mbar_init(mb0 + 8, 1);
        asm volatile("fence.proxy.async.shared::cta;" ::: "memory");
    }
    __syncthreads();

    // ---- prologue: prefetch tiles t0 (stage0) and t0+GRID (stage1) ----
    const int t0 = blockIdx.x;
    if (tid == 0) {
        mbar_expect_tx(mb0, STAGE_B);
        bulk_g2s(data_s,          in + (size_t)t0 * TILE_F, TILE_B, mb0);
        bulk_g2s(data_s + TILE_B, tg + (size_t)t0 * TILE_F, TILE_B, mb0);
        int t1 = t0 + GRID;
        if (t1 < NT) {
            mbar_expect_tx(mb0 + 8, STAGE_B);
            bulk_g2s(data_s + STAGE_B,          in + (size_t)t1 * TILE_F, TILE_B, mb0 + 8);
            bulk_g2s(data_s + STAGE_B + TILE_B, tg + (size_t)t1 * TILE_F, TILE_B, mb0 + 8);
        }
    }

    float acc = 0.0f;

    // ---- per-tile body (stage p, parity ph) ----
    auto process = [&](int t, int p, int ph) {
        mbar_wait(mb0 + 8u * p, (uint32_t)ph);

        const float* in_sm = (const float*)(smraw + OFF_DATA + p * STAGE_B);
        const float* tg_sm = (const float*)(smraw + OFF_DATA + p * STAGE_B + TILE_B);
        const float* ri = in_sm + row * DIM + kbeg;
        const float* rt = tg_sm + row * DIM + kbeg;

        float P = 0.0f, Tn = 0.0f, U = 0.0f;     // Tn = -T
#pragma unroll
        for (int k = 0; k < 22; k++) {
            if (k < kcnt) {
                float d  = fabsf(ri[k] - rt[k]);
                float fk = fkbeg + (float)k;
                U  = fmaf(d, fmaf(fk, P, Tn), U);
                P += d;
                Tn = fmaf(-fk, d, Tn);
            }
        }
        sP[tid] = P; sT[tid] = -Tn; sU[tid] = U;
        __syncthreads();                          // stage p fully consumed

        // refill stage p with tile t + 2*GRID immediately (decoupled TMA stream)
        int tn = t + 2 * GRID;
        if (tid == 0 && tn < NT) {
            uint32_t mb = mb0 + 8u * p;
            uint32_t ds = data_s + (uint32_t)(p * STAGE_B);
            mbar_expect_tx(mb, STAGE_B);
            bulk_g2s(ds,          in + (size_t)tn * TILE_F, TILE_B, mb);
            bulk_g2s(ds + TILE_B, tg + (size_t)tn * TILE_F, TILE_B, mb);
        }

        // per-row combine of 4 segment partials (threads 0..63)
        if (tid < TROWS) {
            float P0 = sP[tid], P1 = sP[64 + tid], P2 = sP[128 + tid], P3 = sP[192 + tid];
            float T0 = sT[tid], T1 = sT[64 + tid], T2 = sT[128 + tid], T3 = sT[192 + tid];
            float Ut = (sU[tid] + sU[64 + tid]) + (sU[128 + tid] + sU[192 + tid]);
            Ut = fmaf(P0, T1, fmaf(-T0, P1, Ut));
            Ut = fmaf(P0, T2, fmaf(-T0, P2, Ut));
            Ut = fmaf(P0, T3, fmaf(-T0, P3, Ut));
            Ut = fmaf(P1, T2, fmaf(-T1, P2, Ut));
            Ut = fmaf(P1, T3, fmaf(-T1, P3, Ut));
            Ut = fmaf(P2, T3, fmaf(-T2, P3, Ut));
            float S = (P0 + P1) + (P2 + P3);
            acc += fmaf(S, S, -(2.0f / (float)DIM) * Ut);
        }
        __syncthreads();                          // protect sP/sT/sU reuse
    };

    int ph0 = 0, ph1 = 0;
    int t = t0;
    while (t < NT) {
        process(t, 0, ph0); ph0 ^= 1;
        t += GRID;
        if (t >= NT) break;
        process(t, 1, ph1); ph1 ^= 1;
        t += GRID;
    }

    // ---- block reduce per-thread accumulators (deterministic) ----
    for (int o = 16; o; o >>= 1)
        acc += __shfl_down_sync(0xffffffffu, acc, o);
    if ((tid & 31) == 0)
        warp_part[tid >> 5] = acc;
    __syncthreads();

    if (tid == 0) {
        float s = 0.0f;
#pragma unroll
        for (int i = 0; i < THREADS / 32; i++)
            s += warp_part[i];
        g_partials[blockIdx.x] = s;
        __threadfence();
        int old = atomicAdd(&g_count, 1);
        s_is_last = (old == GRID - 1);
    }
    __syncthreads();

    // ---- last-arriving block: final deterministic reduce in double ----
    if (s_is_last) {
        __shared__ double sd[THREADS];
        double a = 0.0;
#pragma unroll
        for (int j = 0; j < (GRID + THREADS - 1) / THREADS; j++) {
            int i = tid + j * THREADS;
            if (i < GRID) a += (double)g_partials[i];
        }
        sd[tid] = a;
        __syncthreads();
        for (int o = THREADS / 2; o; o >>= 1) {
            if (tid < o) sd[tid] += sd[tid + o];
            __syncthreads();
        }
        if (tid == 0) {
            out[0] = (float)(0.1 * sd[0]);
            g_count = 0;                          // self-reset for next replay
        }
    }
}

extern "C" void kernel_launch(void* const* d_in, const int* in_sizes, int n_in,
                              void* d_out, int out_size)
{
    const float* in = (const float*)d_in[0];
    const float* tg = (const float*)d_in[1];
    float* out = (float*)d_out;

    cudaFuncSetAttribute(qfd_tma2,
                         cudaFuncAttributeMaxDynamicSharedMemorySize, SMEM_TOTAL);
    qfd_tma2<<<GRID, THREADS, SMEM_TOTAL>>>(in, tg, out);
}